// round 2
// baseline (speedup 1.0000x reference)
#include <cuda_runtime.h>

#define B_SZ     1024
#define CH       64
#define NI       100000
#define HIST     50
#define BM       64
#define BN       128
#define NTHREADS 128

__device__ double g_loss;

__global__ void k_zero() { g_loss = 0.0; }

// C[b, n] = sum_k U[uid[b], k] * I[n, k]; fused sum of squares into g_loss.
template<bool ALIGNED>
__global__ __launch_bounds__(NTHREADS)
void k_gemm(const float* __restrict__ user_emb,
            const float* __restrict__ item_emb,
            const int*   __restrict__ uid,
            float*       __restrict__ pref)
{
    __shared__ float Us[CH][BM];   // 16 KB, k-major user tile
    __shared__ float Is[CH][BN];   // 32 KB, k-major item tile (total = 48 KB exactly)

    const int t  = threadIdx.x;
    const int tx = t & 15;         // 0..15 -> 8 cols each
    const int ty = t >> 4;         // 0..7  -> 8 rows each
    const int brow = blockIdx.y * BM;
    const int bcol = blockIdx.x * BN;

    // ---- load user tile (gather rows via uid), store transposed (k-major) ----
    #pragma unroll
    for (int it = 0; it < (BM * CH / 4) / NTHREADS; it++) {   // 8 iters
        int f = t + it * NTHREADS;       // float4 id
        int m = f >> 4;                  // 0..63
        int q = f & 15;                  // float4 within the 64-float row
        int u = __ldg(&uid[brow + m]);
        float4 v = *reinterpret_cast<const float4*>(user_emb + (size_t)u * CH + q * 4);
        Us[q * 4 + 0][m] = v.x;
        Us[q * 4 + 1][m] = v.y;
        Us[q * 4 + 2][m] = v.z;
        Us[q * 4 + 3][m] = v.w;
    }
    // ---- load item tile, store transposed (k-major); zero-fill past NI ----
    #pragma unroll
    for (int it = 0; it < (BN * CH / 4) / NTHREADS; it++) {   // 16 iters
        int f = t + it * NTHREADS;
        int n = f >> 4;                  // 0..127
        int q = f & 15;
        int col = bcol + n;
        float4 v = make_float4(0.f, 0.f, 0.f, 0.f);
        if (col < NI)
            v = *reinterpret_cast<const float4*>(item_emb + (size_t)col * CH + q * 4);
        Is[q * 4 + 0][n] = v.x;
        Is[q * 4 + 1][n] = v.y;
        Is[q * 4 + 2][n] = v.z;
        Is[q * 4 + 3][n] = v.w;
    }
    __syncthreads();

    float acc[8][8];
    #pragma unroll
    for (int i = 0; i < 8; i++)
        #pragma unroll
        for (int j = 0; j < 8; j++) acc[i][j] = 0.f;

    // ---- main K loop: conflict-free float4 smem reads, 64 FFMA per k ----
    #pragma unroll 8
    for (int k = 0; k < CH; k++) {
        float4 a0 = *reinterpret_cast<const float4*>(&Us[k][ty * 8]);
        float4 a1 = *reinterpret_cast<const float4*>(&Us[k][ty * 8 + 4]);
        float4 b0 = *reinterpret_cast<const float4*>(&Is[k][tx * 8]);
        float4 b1 = *reinterpret_cast<const float4*>(&Is[k][tx * 8 + 4]);
        float a[8] = {a0.x, a0.y, a0.z, a0.w, a1.x, a1.y, a1.z, a1.w};
        float b[8] = {b0.x, b0.y, b0.z, b0.w, b1.x, b1.y, b1.z, b1.w};
        #pragma unroll
        for (int i = 0; i < 8; i++)
            #pragma unroll
            for (int j = 0; j < 8; j++)
                acc[i][j] = fmaf(a[i], b[j], acc[i][j]);
    }

    // ---- fused loss partial: sum of squares (zero-padded cols contribute 0) ----
    float ls = 0.f;
    #pragma unroll
    for (int i = 0; i < 8; i++)
        #pragma unroll
        for (int j = 0; j < 8; j++)
            ls = fmaf(acc[i][j], acc[i][j], ls);
    #pragma unroll
    for (int o = 16; o > 0; o >>= 1)
        ls += __shfl_xor_sync(0xffffffffu, ls, o);

    __syncthreads();   // everyone done reading Us/Is -> safe to reuse smem

    float* red = &Us[0][0];
    if ((t & 31) == 0) red[t >> 5] = ls;

    if (ALIGNED) {
        // direct vectorized stores (pref 16B-aligned)
        #pragma unroll
        for (int i = 0; i < 8; i++) {
            int row = brow + ty * 8 + i;
            int col = bcol + tx * 8;
            if (col < NI) {   // NI % 8 == 0 so whole 8-group is valid together
                float* p = pref + (size_t)row * NI + col;
                *reinterpret_cast<float4*>(p)     = make_float4(acc[i][0], acc[i][1], acc[i][2], acc[i][3]);
                *reinterpret_cast<float4*>(p + 4) = make_float4(acc[i][4], acc[i][5], acc[i][6], acc[i][7]);
            }
        }
        __syncthreads();
        if (t == 0) atomicAdd(&g_loss, (double)(red[0] + red[1] + red[2] + red[3]));
    } else {
        // pref is off-by-one-float (loss at d_out[0]) -> stage tile in smem,
        // then coalesced scalar stores.
        float* stage = &Is[0][0];            // 64*128 floats = 32 KB
        #pragma unroll
        for (int i = 0; i < 8; i++) {
            float* s = &stage[(ty * 8 + i) * BN + tx * 8];
            *reinterpret_cast<float4*>(s)     = make_float4(acc[i][0], acc[i][1], acc[i][2], acc[i][3]);
            *reinterpret_cast<float4*>(s + 4) = make_float4(acc[i][4], acc[i][5], acc[i][6], acc[i][7]);
        }
        __syncthreads();
        if (t == 0) atomicAdd(&g_loss, (double)(red[0] + red[1] + red[2] + red[3]));
        #pragma unroll 4
        for (int idx = t; idx < BM * BN; idx += NTHREADS) {
            int r = idx >> 7;          // / BN
            int c = idx & (BN - 1);
            int col = bcol + c;
            if (col < NI)
                pref[(size_t)(brow + r) * NI + col] = stage[idx];
        }
    }
}

// Positive-mask correction: loss += sum over UNIQUE (row, seq[row][j]) of (1 - 2*s).
// Dedup matches jnp mask-scatter semantics (duplicates set the same bit once).
__global__ void k_pos(const int* __restrict__ seq, const float* __restrict__ pref)
{
    __shared__ int   s[HIST];
    __shared__ float ws[2];
    const int row = blockIdx.x;
    const int t   = threadIdx.x;     // 64 threads
    if (t < HIST) s[t] = seq[row * HIST + t];
    __syncthreads();

    float c = 0.f;
    if (t < HIST) {
        int v = s[t];
        bool dup = false;
        for (int j = 0; j < t; j++) dup |= (s[j] == v);
        if (!dup)
            c = 1.0f - 2.0f * pref[(size_t)row * NI + v];
    }
    #pragma unroll
    for (int o = 16; o > 0; o >>= 1)
        c += __shfl_xor_sync(0xffffffffu, c, o);
    if ((t & 31) == 0) ws[t >> 5] = c;
    __syncthreads();
    if (t == 0) atomicAdd(&g_loss, (double)(ws[0] + ws[1]));
}

__global__ void k_fin(float* loss_out) { *loss_out = (float)g_loss; }

extern "C" void kernel_launch(void* const* d_in, const int* in_sizes, int n_in,
                              void* d_out, int out_size)
{
    const float* user_emb = (const float*)d_in[0];
    const float* item_emb = (const float*)d_in[1];
    const int*   uid      = (const int*)d_in[2];
    const int*   seq      = (const int*)d_in[3];
    float* out = (float*)d_out;

    const long long full = (long long)B_SZ * NI;   // 102,400,000
    float* pref;
    float* loss_ptr = nullptr;
    bool aligned;

    if ((long long)out_size == full + 1) {
        // tuple order (loss, pref_score): scalar first, matrix after.
        loss_ptr = out;
        pref     = out + 1;
        aligned  = false;
    } else {
        pref    = out;
        aligned = true;
        if ((long long)out_size >= full + 1) loss_ptr = out + full;
    }

    dim3 grid((NI + BN - 1) / BN, B_SZ / BM);   // 782 x 16
    k_zero<<<1, 1>>>();
    if (aligned) k_gemm<true ><<<grid, NTHREADS>>>(user_emb, item_emb, uid, pref);
    else         k_gemm<false><<<grid, NTHREADS>>>(user_emb, item_emb, uid, pref);
    k_pos<<<B_SZ, 64>>>(seq, pref);
    if (loss_ptr) k_fin<<<1, 1>>>(loss_ptr);
}

// round 3
// speedup vs baseline: 1.0525x; 1.0525x over previous
#include <cuda_runtime.h>

#define B_SZ     1024
#define CH       64
#define NI       100000
#define HIST     50
#define BM       64
#define BN       128
#define NTHREADS 128

__device__ double g_loss;

__global__ void k_zero() { g_loss = 0.0; }

// C[b, n] = sum_k U[uid[b], k] * I[n, k]; fused sum of squares into g_loss.
template<bool ALIGNED>
__global__ __launch_bounds__(NTHREADS)
void k_gemm(const float* __restrict__ user_emb,
            const float* __restrict__ item_emb,
            const int*   __restrict__ uid,
            float*       __restrict__ pref)
{
    __shared__ float Us[CH][BM];   // 16 KB, k-major user tile
    __shared__ float Is[CH][BN];   // 32 KB, k-major item tile (total = 48 KB exactly)

    const int t  = threadIdx.x;
    const int tx = t & 15;         // 0..15 -> 8 cols each
    const int ty = t >> 4;         // 0..7  -> 8 rows each
    const int brow = blockIdx.y * BM;
    const int bcol = blockIdx.x * BN;

    // ---- load user tile (gather rows via uid), store transposed (k-major) ----
    #pragma unroll
    for (int it = 0; it < (BM * CH / 4) / NTHREADS; it++) {   // 8 iters
        int f = t + it * NTHREADS;       // float4 id
        int m = f >> 4;                  // 0..63
        int q = f & 15;                  // float4 within the 64-float row
        int u = __ldg(&uid[brow + m]);
        float4 v = *reinterpret_cast<const float4*>(user_emb + (size_t)u * CH + q * 4);
        Us[q * 4 + 0][m] = v.x;
        Us[q * 4 + 1][m] = v.y;
        Us[q * 4 + 2][m] = v.z;
        Us[q * 4 + 3][m] = v.w;
    }
    // ---- load item tile, store transposed (k-major); zero-fill past NI ----
    #pragma unroll
    for (int it = 0; it < (BN * CH / 4) / NTHREADS; it++) {   // 16 iters
        int f = t + it * NTHREADS;
        int n = f >> 4;                  // 0..127
        int q = f & 15;
        int col = bcol + n;
        float4 v = make_float4(0.f, 0.f, 0.f, 0.f);
        if (col < NI)
            v = *reinterpret_cast<const float4*>(item_emb + (size_t)col * CH + q * 4);
        Is[q * 4 + 0][n] = v.x;
        Is[q * 4 + 1][n] = v.y;
        Is[q * 4 + 2][n] = v.z;
        Is[q * 4 + 3][n] = v.w;
    }
    __syncthreads();

    float acc[8][8];
    #pragma unroll
    for (int i = 0; i < 8; i++)
        #pragma unroll
        for (int j = 0; j < 8; j++) acc[i][j] = 0.f;

    // ---- main K loop: conflict-free float4 smem reads, 64 FFMA per k ----
    #pragma unroll 8
    for (int k = 0; k < CH; k++) {
        float4 a0 = *reinterpret_cast<const float4*>(&Us[k][ty * 8]);
        float4 a1 = *reinterpret_cast<const float4*>(&Us[k][ty * 8 + 4]);
        float4 b0 = *reinterpret_cast<const float4*>(&Is[k][tx * 8]);
        float4 b1 = *reinterpret_cast<const float4*>(&Is[k][tx * 8 + 4]);
        float a[8] = {a0.x, a0.y, a0.z, a0.w, a1.x, a1.y, a1.z, a1.w};
        float b[8] = {b0.x, b0.y, b0.z, b0.w, b1.x, b1.y, b1.z, b1.w};
        #pragma unroll
        for (int i = 0; i < 8; i++)
            #pragma unroll
            for (int j = 0; j < 8; j++)
                acc[i][j] = fmaf(a[i], b[j], acc[i][j]);
    }

    // ---- fused loss partial: sum of squares (zero-padded cols contribute 0) ----
    float ls = 0.f;
    #pragma unroll
    for (int i = 0; i < 8; i++)
        #pragma unroll
        for (int j = 0; j < 8; j++)
            ls = fmaf(acc[i][j], acc[i][j], ls);
    #pragma unroll
    for (int o = 16; o > 0; o >>= 1)
        ls += __shfl_xor_sync(0xffffffffu, ls, o);

    __syncthreads();   // everyone done reading Us/Is -> safe to reuse smem

    float* red = &Us[0][0];
    if ((t & 31) == 0) red[t >> 5] = ls;

    if (ALIGNED) {
        // direct vectorized stores (pref 16B-aligned)
        #pragma unroll
        for (int i = 0; i < 8; i++) {
            int row = brow + ty * 8 + i;
            int col = bcol + tx * 8;
            if (col < NI) {   // NI % 8 == 0 so whole 8-group is valid together
                float* p = pref + (size_t)row * NI + col;
                *reinterpret_cast<float4*>(p)     = make_float4(acc[i][0], acc[i][1], acc[i][2], acc[i][3]);
                *reinterpret_cast<float4*>(p + 4) = make_float4(acc[i][4], acc[i][5], acc[i][6], acc[i][7]);
            }
        }
        __syncthreads();
        if (t == 0) atomicAdd(&g_loss, (double)(red[0] + red[1] + red[2] + red[3]));
    } else {
        // pref is off-by-one-float (loss at d_out[0]) -> stage tile in smem,
        // then coalesced scalar stores.
        float* stage = &Is[0][0];            // 64*128 floats = 32 KB
        #pragma unroll
        for (int i = 0; i < 8; i++) {
            float* s = &stage[(ty * 8 + i) * BN + tx * 8];
            *reinterpret_cast<float4*>(s)     = make_float4(acc[i][0], acc[i][1], acc[i][2], acc[i][3]);
            *reinterpret_cast<float4*>(s + 4) = make_float4(acc[i][4], acc[i][5], acc[i][6], acc[i][7]);
        }
        __syncthreads();
        if (t == 0) atomicAdd(&g_loss, (double)(red[0] + red[1] + red[2] + red[3]));
        #pragma unroll 4
        for (int idx = t; idx < BM * BN; idx += NTHREADS) {
            int r = idx >> 7;          // / BN
            int c = idx & (BN - 1);
            int col = bcol + c;
            if (col < NI)
                pref[(size_t)(brow + r) * NI + col] = stage[idx];
        }
    }
}

// Positive-mask correction: loss += sum over UNIQUE (row, seq[row][j]) of (1 - 2*s).
// Dedup matches jnp mask-scatter semantics (duplicates set the same bit once).
__global__ void k_pos(const int* __restrict__ seq, const float* __restrict__ pref)
{
    __shared__ int   s[HIST];
    __shared__ float ws[2];
    const int row = blockIdx.x;
    const int t   = threadIdx.x;     // 64 threads
    if (t < HIST) s[t] = seq[row * HIST + t];
    __syncthreads();

    float c = 0.f;
    if (t < HIST) {
        int v = s[t];
        bool dup = false;
        for (int j = 0; j < t; j++) dup |= (s[j] == v);
        if (!dup)
            c = 1.0f - 2.0f * pref[(size_t)row * NI + v];
    }
    #pragma unroll
    for (int o = 16; o > 0; o >>= 1)
        c += __shfl_xor_sync(0xffffffffu, c, o);
    if ((t & 31) == 0) ws[t >> 5] = c;
    __syncthreads();
    if (t == 0) atomicAdd(&g_loss, (double)(ws[0] + ws[1]));
}

__global__ void k_fin(float* loss_out) { *loss_out = (float)g_loss; }

extern "C" void kernel_launch(void* const* d_in, const int* in_sizes, int n_in,
                              void* d_out, int out_size)
{
    const float* user_emb = (const float*)d_in[0];
    const float* item_emb = (const float*)d_in[1];
    const int*   uid      = (const int*)d_in[2];
    const int*   seq      = (const int*)d_in[3];
    float* out = (float*)d_out;

    const long long full = (long long)B_SZ * NI;   // 102,400,000
    float* pref;
    float* loss_ptr = nullptr;
    bool aligned;

    if ((long long)out_size == full + 1) {
        // tuple order (loss, pref_score): scalar first, matrix after.
        loss_ptr = out;
        pref     = out + 1;
        aligned  = false;
    } else {
        pref    = out;
        aligned = true;
        if ((long long)out_size >= full + 1) loss_ptr = out + full;
    }

    dim3 grid((NI + BN - 1) / BN, B_SZ / BM);   // 782 x 16
    k_zero<<<1, 1>>>();
    if (aligned) k_gemm<true ><<<grid, NTHREADS>>>(user_emb, item_emb, uid, pref);
    else         k_gemm<false><<<grid, NTHREADS>>>(user_emb, item_emb, uid, pref);
    k_pos<<<B_SZ, 64>>>(seq, pref);
    if (loss_ptr) k_fin<<<1, 1>>>(loss_ptr);
}

// round 4
// speedup vs baseline: 1.0583x; 1.0055x over previous
#include <cuda_runtime.h>

#define B_SZ     1024
#define CH       64
#define NI       100000
#define HIST     50
#define BM       64
#define BN       128
#define NTHREADS 128

__device__ double g_loss;

__global__ void k_zero() { g_loss = 0.0; }

// C[b, n] = sum_k U[uid[b], k] * I[n, k]; fused sum of squares into g_loss.
template<bool ALIGNED>
__global__ __launch_bounds__(NTHREADS)
void k_gemm(const float* __restrict__ user_emb,
            const float* __restrict__ item_emb,
            const int*   __restrict__ uid,
            float*       __restrict__ pref)
{
    __shared__ float Us[CH][BM];   // 16 KB, k-major user tile
    __shared__ float Is[CH][BN];   // 32 KB, k-major item tile (total = 48 KB exactly)

    const int t  = threadIdx.x;
    const int tx = t & 15;         // 0..15 -> 8 cols each
    const int ty = t >> 4;         // 0..7  -> 8 rows each
    const int brow = blockIdx.y * BM;
    const int bcol = blockIdx.x * BN;

    // ---- load user tile (gather rows via uid), store transposed (k-major) ----
    #pragma unroll
    for (int it = 0; it < (BM * CH / 4) / NTHREADS; it++) {   // 8 iters
        int f = t + it * NTHREADS;       // float4 id
        int m = f >> 4;                  // 0..63
        int q = f & 15;                  // float4 within the 64-float row
        int u = __ldg(&uid[brow + m]);
        float4 v = *reinterpret_cast<const float4*>(user_emb + (size_t)u * CH + q * 4);
        Us[q * 4 + 0][m] = v.x;
        Us[q * 4 + 1][m] = v.y;
        Us[q * 4 + 2][m] = v.z;
        Us[q * 4 + 3][m] = v.w;
    }
    // ---- load item tile, store transposed (k-major); zero-fill past NI ----
    #pragma unroll
    for (int it = 0; it < (BN * CH / 4) / NTHREADS; it++) {   // 16 iters
        int f = t + it * NTHREADS;
        int n = f >> 4;                  // 0..127
        int q = f & 15;
        int col = bcol + n;
        float4 v = make_float4(0.f, 0.f, 0.f, 0.f);
        if (col < NI)
            v = *reinterpret_cast<const float4*>(item_emb + (size_t)col * CH + q * 4);
        Is[q * 4 + 0][n] = v.x;
        Is[q * 4 + 1][n] = v.y;
        Is[q * 4 + 2][n] = v.z;
        Is[q * 4 + 3][n] = v.w;
    }
    __syncthreads();

    float acc[8][8];
    #pragma unroll
    for (int i = 0; i < 8; i++)
        #pragma unroll
        for (int j = 0; j < 8; j++) acc[i][j] = 0.f;

    // ---- main K loop: conflict-free float4 smem reads, 64 FFMA per k ----
    #pragma unroll 8
    for (int k = 0; k < CH; k++) {
        float4 a0 = *reinterpret_cast<const float4*>(&Us[k][ty * 8]);
        float4 a1 = *reinterpret_cast<const float4*>(&Us[k][ty * 8 + 4]);
        float4 b0 = *reinterpret_cast<const float4*>(&Is[k][tx * 8]);
        float4 b1 = *reinterpret_cast<const float4*>(&Is[k][tx * 8 + 4]);
        float a[8] = {a0.x, a0.y, a0.z, a0.w, a1.x, a1.y, a1.z, a1.w};
        float b[8] = {b0.x, b0.y, b0.z, b0.w, b1.x, b1.y, b1.z, b1.w};
        #pragma unroll
        for (int i = 0; i < 8; i++)
            #pragma unroll
            for (int j = 0; j < 8; j++)
                acc[i][j] = fmaf(a[i], b[j], acc[i][j]);
    }

    // ---- fused loss partial: sum of squares (zero-padded cols contribute 0) ----
    float ls = 0.f;
    #pragma unroll
    for (int i = 0; i < 8; i++)
        #pragma unroll
        for (int j = 0; j < 8; j++)
            ls = fmaf(acc[i][j], acc[i][j], ls);
    #pragma unroll
    for (int o = 16; o > 0; o >>= 1)
        ls += __shfl_xor_sync(0xffffffffu, ls, o);

    __syncthreads();   // everyone done reading Us/Is -> safe to reuse smem

    float* red = &Us[0][0];
    if ((t & 31) == 0) red[t >> 5] = ls;

    if (ALIGNED) {
        // direct vectorized stores (pref 16B-aligned)
        #pragma unroll
        for (int i = 0; i < 8; i++) {
            int row = brow + ty * 8 + i;
            int col = bcol + tx * 8;
            if (col < NI) {   // NI % 8 == 0 so whole 8-group is valid together
                float* p = pref + (size_t)row * NI + col;
                *reinterpret_cast<float4*>(p)     = make_float4(acc[i][0], acc[i][1], acc[i][2], acc[i][3]);
                *reinterpret_cast<float4*>(p + 4) = make_float4(acc[i][4], acc[i][5], acc[i][6], acc[i][7]);
            }
        }
        __syncthreads();
        if (t == 0) atomicAdd(&g_loss, (double)(red[0] + red[1] + red[2] + red[3]));
    } else {
        // pref is off-by-one-float (loss at d_out[0]) -> stage tile in smem,
        // then coalesced scalar stores.
        float* stage = &Is[0][0];            // 64*128 floats = 32 KB
        #pragma unroll
        for (int i = 0; i < 8; i++) {
            float* s = &stage[(ty * 8 + i) * BN + tx * 8];
            *reinterpret_cast<float4*>(s)     = make_float4(acc[i][0], acc[i][1], acc[i][2], acc[i][3]);
            *reinterpret_cast<float4*>(s + 4) = make_float4(acc[i][4], acc[i][5], acc[i][6], acc[i][7]);
        }
        __syncthreads();
        if (t == 0) atomicAdd(&g_loss, (double)(red[0] + red[1] + red[2] + red[3]));
        #pragma unroll 4
        for (int idx = t; idx < BM * BN; idx += NTHREADS) {
            int r = idx >> 7;          // / BN
            int c = idx & (BN - 1);
            int col = bcol + c;
            if (col < NI)
                pref[(size_t)(brow + r) * NI + col] = stage[idx];
        }
    }
}

// Positive-mask correction: loss += sum over UNIQUE (row, seq[row][j]) of (1 - 2*s).
// Dedup matches jnp mask-scatter semantics (duplicates set the same bit once).
__global__ void k_pos(const int* __restrict__ seq, const float* __restrict__ pref)
{
    __shared__ int   s[HIST];
    __shared__ float ws[2];
    const int row = blockIdx.x;
    const int t   = threadIdx.x;     // 64 threads
    if (t < HIST) s[t] = seq[row * HIST + t];
    __syncthreads();

    float c = 0.f;
    if (t < HIST) {
        int v = s[t];
        bool dup = false;
        for (int j = 0; j < t; j++) dup |= (s[j] == v);
        if (!dup)
            c = 1.0f - 2.0f * pref[(size_t)row * NI + v];
    }
    #pragma unroll
    for (int o = 16; o > 0; o >>= 1)
        c += __shfl_xor_sync(0xffffffffu, c, o);
    if ((t & 31) == 0) ws[t >> 5] = c;
    __syncthreads();
    if (t == 0) atomicAdd(&g_loss, (double)(ws[0] + ws[1]));
}

__global__ void k_fin(float* loss_out) { *loss_out = (float)g_loss; }

extern "C" void kernel_launch(void* const* d_in, const int* in_sizes, int n_in,
                              void* d_out, int out_size)
{
    const float* user_emb = (const float*)d_in[0];
    const float* item_emb = (const float*)d_in[1];
    const int*   uid      = (const int*)d_in[2];
    const int*   seq      = (const int*)d_in[3];
    float* out = (float*)d_out;

    const long long full = (long long)B_SZ * NI;   // 102,400,000
    float* pref;
    float* loss_ptr = nullptr;
    bool aligned;

    if ((long long)out_size == full + 1) {
        // tuple order (loss, pref_score): scalar first, matrix after.
        loss_ptr = out;
        pref     = out + 1;
        aligned  = false;
    } else {
        pref    = out;
        aligned = true;
        if ((long long)out_size >= full + 1) loss_ptr = out + full;
    }

    dim3 grid((NI + BN - 1) / BN, B_SZ / BM);   // 782 x 16
    k_zero<<<1, 1>>>();
    if (aligned) k_gemm<true ><<<grid, NTHREADS>>>(user_emb, item_emb, uid, pref);
    else         k_gemm<false><<<grid, NTHREADS>>>(user_emb, item_emb, uid, pref);
    k_pos<<<B_SZ, 64>>>(seq, pref);
    if (loss_ptr) k_fin<<<1, 1>>>(loss_ptr);
}